// round 1
// baseline (speedup 1.0000x reference)
#include <cuda_runtime.h>

// Problem constants
#define Bn   64
#define Dn   128
#define LCn  1024
#define LQn  128
#define TCn  128
#define NTn  8    // LCn / TCn
#define NEGV (-1e30f)

// Scratch (static device globals — no runtime allocation)
__device__ float g_S  [(size_t)Bn * LCn * LQn];        // 33.5 MB  S[b][c][q]
__device__ float g_Tp [(size_t)Bn * NTn * LQn * Dn];   // 33.5 MB  partial T per c-tile
__device__ float g_T  [(size_t)Bn * LQn * Dn];         // 4 MB     T[b][q][d]
__device__ float g_cp [Bn * NTn * LQn * 2];            // per-tile column (S2) LSE partials
__device__ float g_cs [Bn * LQn * 2];                  // combined column stats (m2, l2)

// ---------------------------------------------------------------------------
// K1: per (b, c-tile): S[c][q] = sum_d C[b,d,c]*w_m[d]*Q[b,d,q] + s_c[c] + s_q[q]
//     write S to global, and per-q (column) max/sumexp partials for S2.
// smem: Qs[128][128], Cs[128][128], sq[128], sc[128], w[384], cmadd[128]
// ---------------------------------------------------------------------------
__global__ __launch_bounds__(256) void k1_S(const float* __restrict__ C,
                                            const float* __restrict__ Q,
                                            const float* __restrict__ cmask,
                                            const float* __restrict__ w)
{
    extern __shared__ float sm[];
    float* Qs    = sm;            // [d][q] stride 128
    float* Cs    = sm + 16384;    // [d][c] stride 128 (later reused as Ss[c][q])
    float* sq    = sm + 32768;
    float* sc    = sm + 32896;
    float* wv    = sm + 33024;    // w_q | w_c | w_m
    float* cmadd = sm + 33408;

    const int b  = blockIdx.y;
    const int t  = blockIdx.x;
    const int c0 = t * TCn;
    const int tid = threadIdx.x;

    for (int i = tid; i < 384; i += 256) wv[i] = w[i];
    if (tid < 128) cmadd[tid] = (1.0f - cmask[b * LCn + c0 + tid]) * NEGV;

    // Load Q[b] (contiguous 128x128)
    {
        const float4* Qg = (const float4*)(Q + (size_t)b * Dn * LQn);
        float4* Qs4 = (float4*)Qs;
        #pragma unroll 4
        for (int i = tid; i < 4096; i += 256) Qs4[i] = Qg[i];
    }
    // Load C tile: Cs[d][c] = C[b, d, c0+c]
    {
        const float* Cg = C + (size_t)b * Dn * LCn + c0;
        #pragma unroll 4
        for (int i = tid; i < 4096; i += 256) {
            int d = i >> 5, x = i & 31;
            ((float4*)(Cs + d * 128))[x] = ((const float4*)(Cg + (size_t)d * LCn))[x];
        }
    }
    __syncthreads();

    // s_q[q] = sum_d Q[d][q]*w_q[d] ; s_c[c] = sum_d C[d][c]*w_c[d]
    if (tid < 128) {
        float s = 0.f;
        #pragma unroll 8
        for (int d = 0; d < 128; d++) s += Qs[d * 128 + tid] * wv[d];
        sq[tid] = s;
    } else {
        const int c = tid - 128;
        float s = 0.f;
        #pragma unroll 8
        for (int d = 0; d < 128; d++) s += Cs[d * 128 + c] * wv[128 + d];
        sc[c] = s;
    }
    __syncthreads();

    // Scale Cs rows by w_m[d]
    #pragma unroll 4
    for (int i = tid; i < 4096; i += 256) {
        int d = i >> 5;
        float m = wv[256 + d];
        float4 v = ((float4*)Cs)[i];
        v.x *= m; v.y *= m; v.z *= m; v.w *= m;
        ((float4*)Cs)[i] = v;
    }
    __syncthreads();

    // GEMM over d: acc[c][q], c = ty*8+i, q = tx*8+j
    const int tx = tid & 15, ty = tid >> 4;
    float acc[8][8];
    #pragma unroll
    for (int i = 0; i < 8; i++)
        #pragma unroll
        for (int j = 0; j < 8; j++) acc[i][j] = 0.f;

    const float* Cb = Cs + ty * 8;
    const float* Qb = Qs + tx * 8;
    for (int d = 0; d < 128; d++) {
        float4 a0 = *(const float4*)(Cb + d * 128);
        float4 a1 = *(const float4*)(Cb + d * 128 + 4);
        float4 q0 = *(const float4*)(Qb + d * 128);
        float4 q1 = *(const float4*)(Qb + d * 128 + 4);
        float av[8] = {a0.x, a0.y, a0.z, a0.w, a1.x, a1.y, a1.z, a1.w};
        float qv[8] = {q0.x, q0.y, q0.z, q0.w, q1.x, q1.y, q1.z, q1.w};
        #pragma unroll
        for (int i = 0; i < 8; i++)
            #pragma unroll
            for (int j = 0; j < 8; j++)
                acc[i][j] = fmaf(av[i], qv[j], acc[i][j]);
    }
    __syncthreads();   // GEMM reads done; safe to reuse Cs as Ss

    float* Ss = Cs;    // Ss[c][q] stride 128
    float sqr[8];
    #pragma unroll
    for (int j = 0; j < 8; j++) sqr[j] = sq[tx * 8 + j];

    float* gS = g_S + ((size_t)(b * LCn + c0)) * LQn;
    #pragma unroll
    for (int i = 0; i < 8; i++) {
        const int c = ty * 8 + i;
        const float scv = sc[c];
        float v[8];
        #pragma unroll
        for (int j = 0; j < 8; j++) v[j] = acc[i][j] + scv + sqr[j];
        float4 v0 = make_float4(v[0], v[1], v[2], v[3]);
        float4 v1 = make_float4(v[4], v[5], v[6], v[7]);
        *(float4*)(Ss + c * 128 + tx * 8)     = v0;
        *(float4*)(Ss + c * 128 + tx * 8 + 4) = v1;
        *(float4*)(gS + (size_t)c * LQn + tx * 8)     = v0;
        *(float4*)(gS + (size_t)c * LQn + tx * 8 + 4) = v1;
    }
    __syncthreads();

    // Column (S2 direction) partial stats: per q over this tile's 128 c rows
    if (tid < 128) {
        const int q = tid;
        float m = -3.4e38f;
        #pragma unroll 8
        for (int c = 0; c < 128; c++) m = fmaxf(m, Ss[c * 128 + q] + cmadd[c]);
        float l = 0.f;
        #pragma unroll 8
        for (int c = 0; c < 128; c++) l += __expf(Ss[c * 128 + q] + cmadd[c] - m);
        float* cp = g_cp + ((b * NTn + t) * LQn + q) * 2;
        cp[0] = m;
        cp[1] = l;
    }
}

// ---------------------------------------------------------------------------
// K2: combine per-tile column partials -> (m2, l2) per (b, q)
// ---------------------------------------------------------------------------
__global__ __launch_bounds__(128) void k2_colstats()
{
    const int b = blockIdx.x, q = threadIdx.x;
    float mt[NTn], lt[NTn];
    float m = -3.4e38f;
    #pragma unroll
    for (int t = 0; t < NTn; t++) {
        const float* cp = g_cp + ((b * NTn + t) * LQn + q) * 2;
        mt[t] = cp[0]; lt[t] = cp[1];
        m = fmaxf(m, mt[t]);
    }
    float l = 0.f;
    #pragma unroll
    for (int t = 0; t < NTn; t++) l += lt[t] * __expf(mt[t] - m);
    g_cs[(b * LQn + q) * 2]     = m;
    g_cs[(b * LQn + q) * 2 + 1] = l;
}

// ---------------------------------------------------------------------------
// K3: per (b, c-tile): Tp[q][d] = sum_c S2[c][q] * C[b,d,c]  (tile-partial)
// smem: Ss[128][128] (S tile -> S2), Cts[128][129] (C transposed), stats
// ---------------------------------------------------------------------------
__global__ __launch_bounds__(256) void k3_Tpart(const float* __restrict__ C,
                                                const float* __restrict__ cmask)
{
    extern __shared__ float sm[];
    float* Ss    = sm;            // [c][q] stride 128
    float* Cts   = sm + 16384;    // [c][d] stride 129 (conflict-free transpose)
    float* cmadd = sm + 32896;
    float* m2    = sm + 33024;
    float* il2   = sm + 33152;

    const int b = blockIdx.y, t = blockIdx.x, c0 = t * TCn;
    const int tid = threadIdx.x;

    {
        const float4* gS = (const float4*)(g_S + ((size_t)(b * LCn + c0)) * LQn);
        #pragma unroll 4
        for (int i = tid; i < 4096; i += 256) ((float4*)Ss)[i] = gS[i];
    }
    {
        const float* Cg = C + (size_t)b * Dn * LCn + c0;
        #pragma unroll 4
        for (int i = tid; i < 16384; i += 256) {
            int d = i >> 7, c = i & 127;
            Cts[c * 129 + d] = Cg[(size_t)d * LCn + c];
        }
    }
    if (tid < 128) {
        cmadd[tid] = (1.0f - cmask[b * LCn + c0 + tid]) * NEGV;
        m2[tid]  = g_cs[(b * LQn + tid) * 2];
        il2[tid] = 1.0f / g_cs[(b * LQn + tid) * 2 + 1];
    }
    __syncthreads();

    // Convert S -> S2 in place
    #pragma unroll 4
    for (int i = tid; i < 16384; i += 256) {
        int c = i >> 7, q = i & 127;
        Ss[i] = __expf(Ss[i] + cmadd[c] - m2[q]) * il2[q];
    }
    __syncthreads();

    // GEMM over c: Tp[q][d], q = ty*8+i, d = tx+16*j
    const int tx = tid & 15, ty = tid >> 4;
    float acc[8][8];
    #pragma unroll
    for (int i = 0; i < 8; i++)
        #pragma unroll
        for (int j = 0; j < 8; j++) acc[i][j] = 0.f;

    for (int c = 0; c < 128; c++) {
        float4 s0 = *(const float4*)(Ss + c * 128 + ty * 8);
        float4 s1 = *(const float4*)(Ss + c * 128 + ty * 8 + 4);
        float sv[8] = {s0.x, s0.y, s0.z, s0.w, s1.x, s1.y, s1.z, s1.w};
        float cv[8];
        #pragma unroll
        for (int j = 0; j < 8; j++) cv[j] = Cts[c * 129 + tx + 16 * j];
        #pragma unroll
        for (int i = 0; i < 8; i++)
            #pragma unroll
            for (int j = 0; j < 8; j++)
                acc[i][j] = fmaf(sv[i], cv[j], acc[i][j]);
    }

    float* tp = g_Tp + (size_t)(b * NTn + t) * LQn * Dn;
    #pragma unroll
    for (int i = 0; i < 8; i++)
        #pragma unroll
        for (int j = 0; j < 8; j++)
            tp[(ty * 8 + i) * Dn + tx + 16 * j] = acc[i][j];
}

// ---------------------------------------------------------------------------
// K3b: reduce 8 tile-partials -> T[b][q][d]   (deterministic, no atomics)
// ---------------------------------------------------------------------------
__global__ __launch_bounds__(256) void k3b_Treduce()
{
    const int idx = blockIdx.x * 256 + threadIdx.x;  // 0 .. B*LQ*D-1 (grid 4096x256)
    const int b = idx >> 14;          // / (LQn*Dn)
    const int r = idx & 16383;
    const size_t base = (size_t)b * NTn * 16384 + r;
    float s = 0.f;
    #pragma unroll
    for (int t = 0; t < NTn; t++) s += g_Tp[base + (size_t)t * 16384];
    g_T[idx] = s;
}

// ---------------------------------------------------------------------------
// K4: per (b, c-tile): row softmax -> S1; A = S1@Qt; Bt = S1@T;
//     write out[b, 0:128, c] = C, [128:256] = A, [256:384] = C*A, [384:512] = C*Bt
// smem: buf0 (Ss then Qt^T, 128*129), S1t[q][c] 128*129, Ts[q][d] 128*128, stats
// ---------------------------------------------------------------------------
__global__ __launch_bounds__(256) void k4_final(const float* __restrict__ C,
                                                const float* __restrict__ Q,
                                                const float* __restrict__ qmask,
                                                float* __restrict__ out)
{
    extern __shared__ float sm[];
    float* buf0  = sm;             // Ss[c][q] stride128, later Qts[q][d] stride129
    float* S1t   = sm + 16512;     // [q][c] stride 129
    float* Ts    = sm + 33024;     // [q][d] stride 128
    float* qmadd = sm + 49408;
    float* m1    = sm + 49536;
    float* il1   = sm + 49664;

    const int b = blockIdx.y, t = blockIdx.x, c0 = t * TCn;
    const int tid = threadIdx.x;

    float* Ss = buf0;
    {
        const float4* gS = (const float4*)(g_S + ((size_t)(b * LCn + c0)) * LQn);
        #pragma unroll 4
        for (int i = tid; i < 4096; i += 256) ((float4*)Ss)[i] = gS[i];
        const float4* gT = (const float4*)(g_T + (size_t)b * LQn * Dn);
        #pragma unroll 4
        for (int i = tid; i < 4096; i += 256) ((float4*)Ts)[i] = gT[i];
    }
    if (tid < 128) qmadd[tid] = (1.0f - qmask[b * LQn + tid]) * NEGV;
    __syncthreads();

    // Row (S1) stats: one warp per row group
    {
        const int warp = tid >> 5, lane = tid & 31;
        for (int c = warp; c < 128; c += 8) {
            float x0 = Ss[c * 128 + lane]      + qmadd[lane];
            float x1 = Ss[c * 128 + lane + 32] + qmadd[lane + 32];
            float x2 = Ss[c * 128 + lane + 64] + qmadd[lane + 64];
            float x3 = Ss[c * 128 + lane + 96] + qmadd[lane + 96];
            float m = fmaxf(fmaxf(x0, x1), fmaxf(x2, x3));
            #pragma unroll
            for (int off = 16; off; off >>= 1)
                m = fmaxf(m, __shfl_xor_sync(0xffffffffu, m, off));
            float l = __expf(x0 - m) + __expf(x1 - m) + __expf(x2 - m) + __expf(x3 - m);
            #pragma unroll
            for (int off = 16; off; off >>= 1)
                l += __shfl_xor_sync(0xffffffffu, l, off);
            if (lane == 0) { m1[c] = m; il1[c] = 1.0f / l; }
        }
    }
    __syncthreads();

    // S1 transposed: S1t[q][c]
    #pragma unroll 4
    for (int i = tid; i < 16384; i += 256) {
        int c = i >> 7, q = i & 127;
        S1t[q * 129 + c] = __expf(Ss[i] + qmadd[q] - m1[c]) * il1[c];
    }
    __syncthreads();

    // Overwrite buf0 with Q transposed: Qts[q][d] = Q[b,d,q]
    float* Qts = buf0;
    {
        const float* gQ = Q + (size_t)b * Dn * LQn;
        #pragma unroll 4
        for (int i = tid; i < 16384; i += 256) {
            int d = i >> 7, q = i & 127;
            Qts[q * 129 + d] = gQ[i];
        }
    }
    __syncthreads();

    const int tx = tid & 15, ty = tid >> 4;
    float* outB = out + (size_t)b * 4 * Dn * LCn;
    const float* Cb = C + (size_t)b * Dn * LCn;

    // ---- GEMM A: A[d][c] = sum_q Qts[q][d] * S1t[q][c];  d = ty*8+i, c = tx+16*j
    {
        float acc[8][8];
        #pragma unroll
        for (int i = 0; i < 8; i++)
            #pragma unroll
            for (int j = 0; j < 8; j++) acc[i][j] = 0.f;
        for (int q = 0; q < 128; q++) {
            float av[8], bv[8];
            #pragma unroll
            for (int i = 0; i < 8; i++) av[i] = Qts[q * 129 + ty * 8 + i];
            #pragma unroll
            for (int j = 0; j < 8; j++) bv[j] = S1t[q * 129 + tx + 16 * j];
            #pragma unroll
            for (int i = 0; i < 8; i++)
                #pragma unroll
                for (int j = 0; j < 8; j++)
                    acc[i][j] = fmaf(av[i], bv[j], acc[i][j]);
        }
        #pragma unroll
        for (int i = 0; i < 8; i++) {
            const int d = ty * 8 + i;
            const float* Crow = Cb + (size_t)d * LCn + c0;
            float* o1 = outB + (size_t)(Dn + d) * LCn + c0;
            float* o2 = outB + (size_t)(2 * Dn + d) * LCn + c0;
            #pragma unroll
            for (int j = 0; j < 8; j++) {
                const int c = tx + 16 * j;
                const float a = acc[i][j];
                o1[c] = a;
                o2[c] = Crow[c] * a;
            }
        }
    }

    // ---- GEMM Bt: Bt[d][c] = sum_q Ts[q][d] * S1t[q][c]
    {
        float acc[8][8];
        #pragma unroll
        for (int i = 0; i < 8; i++)
            #pragma unroll
            for (int j = 0; j < 8; j++) acc[i][j] = 0.f;
        for (int q = 0; q < 128; q++) {
            float av[8], bv[8];
            #pragma unroll
            for (int i = 0; i < 8; i++) av[i] = Ts[q * 128 + ty * 8 + i];
            #pragma unroll
            for (int j = 0; j < 8; j++) bv[j] = S1t[q * 129 + tx + 16 * j];
            #pragma unroll
            for (int i = 0; i < 8; i++)
                #pragma unroll
                for (int j = 0; j < 8; j++)
                    acc[i][j] = fmaf(av[i], bv[j], acc[i][j]);
        }
        #pragma unroll
        for (int i = 0; i < 8; i++) {
            const int d = ty * 8 + i;
            const float* Crow = Cb + (size_t)d * LCn + c0;
            float* o3 = outB + (size_t)(3 * Dn + d) * LCn + c0;
            #pragma unroll
            for (int j = 0; j < 8; j++) {
                const int c = tx + 16 * j;
                o3[c] = Crow[c] * acc[i][j];
            }
        }
    }

    // ---- Section 0: out[b, f, c0+..] = C[b, f, c0+..]
    #pragma unroll 4
    for (int i = tid; i < 4096; i += 256) {
        int f = i >> 5, x = i & 31;
        ((float4*)(outB + (size_t)f * LCn + c0))[x] =
            ((const float4*)(Cb + (size_t)f * LCn + c0))[x];
    }
}

// ---------------------------------------------------------------------------
extern "C" void kernel_launch(void* const* d_in, const int* in_sizes, int n_in,
                              void* d_out, int out_size)
{
    const float* C     = (const float*)d_in[0];
    const float* Q     = (const float*)d_in[1];
    const float* cmask = (const float*)d_in[2];
    const float* qmask = (const float*)d_in[3];
    const float* w     = (const float*)d_in[4];
    float* out = (float*)d_out;

    const int smem1 = 33536 * 4;   // 134,144 B
    const int smem3 = 33280 * 4;   // 133,120 B
    const int smem4 = 49792 * 4;   // 199,168 B
    cudaFuncSetAttribute(k1_S,     cudaFuncAttributeMaxDynamicSharedMemorySize, smem1);
    cudaFuncSetAttribute(k3_Tpart, cudaFuncAttributeMaxDynamicSharedMemorySize, smem3);
    cudaFuncSetAttribute(k4_final, cudaFuncAttributeMaxDynamicSharedMemorySize, smem4);

    dim3 grid(NTn, Bn);
    k1_S<<<grid, 256, smem1>>>(C, Q, cmask, w);
    k2_colstats<<<Bn, 128>>>();
    k3_Tpart<<<grid, 256, smem3>>>(C, cmask);
    k3b_Treduce<<<4096, 256>>>();
    k4_final<<<grid, 256, smem4>>>(C, Q, qmask, out);
}